// round 1
// baseline (speedup 1.0000x reference)
#include <cuda_runtime.h>
#include <cuda_bf16.h>
#include <cstdint>

// Problem constants
#define NN 4096
#define BB 16
#define CC 256
#define HH 128
#define C2 512
#define NTOK (NN*BB)       // 65536
#define MAXSEL 2048        // min_cnt <= N/2

// GEMM tiling
#define BM 64
#define BN 128
#define BK 16

// -------------------- device scratch (no allocations allowed) --------------------
__device__ float g_sig[NTOK];                 // [b][n]
__device__ unsigned char g_valid[NTOK];       // [b][n]
__device__ int g_mask_kind;                   // 0=u8, 1=i32, 2=f32
__device__ int g_split_idx[BB*MAXSEL];
__device__ int g_discard_idx[BB*MAXSEL];
__device__ int g_mc[BB];

// -------------------- mask dtype detection --------------------
// Reads only the first B*N bytes (safe for u8/i32/f32 interpretations).
// int32 0/1: bytes at i%4!=0 are all zero. float32 1.0f has byte 0x3f. bool: 0/1 bytes everywhere.
__global__ void detect_mask_kernel(const unsigned char* __restrict__ m) {
    __shared__ int f3, foff;
    if (threadIdx.x == 0) { f3 = 0; foff = 0; }
    __syncthreads();
    int l3 = 0, loff = 0;
    for (int i = threadIdx.x; i < NTOK; i += 256) {
        unsigned char v = m[i];
        if (v == 0x3f) l3 = 1;
        if (v && (i & 3)) loff = 1;
    }
    if (l3) f3 = 1;
    if (loff) foff = 1;
    __syncthreads();
    if (threadIdx.x == 0) g_mask_kind = f3 ? 2 : (foff ? 0 : 1);
}

__global__ void expand_mask_kernel(const void* __restrict__ m) {
    int i = blockIdx.x * 256 + threadIdx.x;
    if (i >= NTOK) return;
    int kind = g_mask_kind;
    int v;
    if (kind == 0)      v = ((const unsigned char*)m)[i];
    else if (kind == 1) v = ((const int*)m)[i];
    else                v = (((const float*)m)[i] != 0.0f);
    g_valid[i] = (v == 0) ? 1 : 0;   // valid = ~mask
}

// -------------------- gating: sig = sigmoid(relu(x@w1+b1)@w2 + b2) --------------------
__global__ void __launch_bounds__(128) gating_kernel(
    const float* __restrict__ x, const float* __restrict__ w1,
    const float* __restrict__ b1v, const float* __restrict__ w2v,
    const float* __restrict__ b2v)
{
    __shared__ float As[BK][BM];
    __shared__ float Bs[BK][BN];
    __shared__ float w2s[HH];
    __shared__ float b1s[HH];
    __shared__ float red[BM][17];

    int tid = threadIdx.x;
    int rg = tid >> 4, cg = tid & 15;
    int tM = blockIdx.x * BM;

    if (tid < HH) { w2s[tid] = w2v[tid]; b1s[tid] = b1v[tid]; }

    float acc[8][8];
    #pragma unroll
    for (int i = 0; i < 8; i++)
        #pragma unroll
        for (int j = 0; j < 8; j++) acc[i][j] = 0.f;

    for (int kt = 0; kt < CC; kt += BK) {
        // A tile: 64 rows x 16 cols = 256 float4, 2 per thread
        #pragma unroll
        for (int r = 0; r < 2; r++) {
            int q = tid + r * 128;
            int row = q >> 2, c4 = q & 3;
            float4 v = *(const float4*)&x[(tM + row) * CC + kt + c4 * 4];
            As[c4*4+0][row] = v.x; As[c4*4+1][row] = v.y;
            As[c4*4+2][row] = v.z; As[c4*4+3][row] = v.w;
        }
        // B tile: 16 rows x 128 cols = 512 float4, 4 per thread
        #pragma unroll
        for (int r = 0; r < 4; r++) {
            int q = tid + r * 128;
            int krow = q >> 5, c4 = q & 31;
            *(float4*)&Bs[krow][c4*4] = *(const float4*)&w1[(kt + krow) * HH + c4 * 4];
        }
        __syncthreads();
        #pragma unroll
        for (int kk = 0; kk < BK; kk++) {
            float a[8], bb[8];
            *(float4*)&a[0]  = *(float4*)&As[kk][rg*8];
            *(float4*)&a[4]  = *(float4*)&As[kk][rg*8+4];
            *(float4*)&bb[0] = *(float4*)&Bs[kk][cg*8];
            *(float4*)&bb[4] = *(float4*)&Bs[kk][cg*8+4];
            #pragma unroll
            for (int i = 0; i < 8; i++)
                #pragma unroll
                for (int j = 0; j < 8; j++)
                    acc[i][j] = fmaf(a[i], bb[j], acc[i][j]);
        }
        __syncthreads();
    }

    // epilogue: relu(h + b1) dot w2
    #pragma unroll
    for (int i = 0; i < 8; i++) {
        float p = 0.f;
        #pragma unroll
        for (int j = 0; j < 8; j++) {
            float h = fmaxf(acc[i][j] + b1s[cg*8+j], 0.f);
            p = fmaf(h, w2s[cg*8+j], p);
        }
        red[rg*8+i][cg] = p;
    }
    __syncthreads();
    if (tid < BM) {
        float lg = b2v[0];
        #pragma unroll
        for (int g = 0; g < 16; g++) lg += red[tid][g];
        float s;
        if (lg >= 0.f) { s = 1.f / (1.f + expf(-lg)); }
        else           { float e = expf(lg); s = e / (1.f + e); }
        int t = tM + tid;              // global row = n*B + b
        g_sig[(t & (BB-1)) * NN + (t >> 4)] = s;
    }
}

// -------------------- selection: per-batch counts, radix-select thresholds, compaction --------------------
__global__ void __launch_bounds__(512) select_kernel() {
    const int T = 512;
    int b = blockIdx.x;
    int tid = threadIdx.x;

    __shared__ unsigned long long keys[NN];   // 32KB
    __shared__ int hist[256];
    __shared__ int sh[T];
    __shared__ int s_cnt, d_cnt, s_k, s_chosen;

    const float* sig = g_sig + b * NN;
    const unsigned char* vd = g_valid + b * NN;

    if (tid == 0) { s_cnt = 0; d_cnt = 0; }
    __syncthreads();
    int cs = 0, cd = 0;
    for (int n = tid; n < NN; n += T) {
        if (vd[n]) { if (sig[n] >= 0.5f) cs++; else cd++; }
    }
    atomicAdd(&s_cnt, cs); atomicAdd(&d_cnt, cd);
    __syncthreads();
    int mc = min(s_cnt, d_cnt);   // MAX_SPLIT=10000 > N/2, irrelevant

    unsigned long long thrS = ~0ull, thrD = ~0ull;
    for (int set = 0; set < 2; set++) {
        __syncthreads();
        for (int n = tid; n < NN; n += T) {
            bool in = vd[n] && ((set == 0) ? (sig[n] >= 0.5f) : (sig[n] < 0.5f));
            unsigned long long key = 0;
            if (in)
                key = ((unsigned long long)__float_as_uint(sig[n]) << 32)
                      | (unsigned)(0xFFFFFFFFu - (unsigned)n);   // tie-break: smaller n ranks first
            keys[n] = key;
        }
        if (tid == 0) s_k = mc;
        __syncthreads();
        if (mc == 0) continue;   // thr stays all-ones -> keep nothing

        unsigned long long prefix = 0;
        for (int d = 7; d >= 0; d--) {
            for (int i = tid; i < 256; i += T) hist[i] = 0;
            __syncthreads();
            unsigned long long hm = (d == 7) ? 0ull : (~0ull << ((d + 1) * 8));
            for (int n = tid; n < NN; n += T) {
                unsigned long long key = keys[n];
                if ((key & hm) == prefix)
                    atomicAdd(&hist[(int)((key >> (d * 8)) & 255)], 1);
            }
            __syncthreads();
            if (tid == 0) {
                int k = s_k, cum = 0, chosen = 0;
                for (int bb2 = 255; bb2 >= 0; bb2--) {
                    int c = hist[bb2];
                    if (k <= cum + c) { chosen = bb2; s_k = k - cum; break; }
                    cum += c;
                }
                s_chosen = chosen;
            }
            __syncthreads();
            prefix |= ((unsigned long long)s_chosen) << (d * 8);
        }
        if (set == 0) thrS = prefix; else thrD = prefix;
    }
    __syncthreads();

    // compaction (two passes: split then discard), each thread owns 8 consecutive n
    for (int set = 0; set < 2; set++) {
        unsigned long long thr = (set == 0) ? thrS : thrD;
        int n0 = tid * 8;
        int cnt = 0;
        unsigned char fl[8];
        #pragma unroll
        for (int q = 0; q < 8; q++) {
            int n = n0 + q;
            bool in = vd[n] && ((set == 0) ? (sig[n] >= 0.5f) : (sig[n] < 0.5f));
            unsigned long long key = ((unsigned long long)__float_as_uint(sig[n]) << 32)
                                     | (unsigned)(0xFFFFFFFFu - (unsigned)n);
            fl[q] = (in && key >= thr) ? 1 : 0;
            cnt += fl[q];
        }
        sh[tid] = cnt;
        __syncthreads();
        for (int off = 1; off < T; off <<= 1) {
            int v = (tid >= off) ? sh[tid - off] : 0;
            __syncthreads();
            sh[tid] += v;
            __syncthreads();
        }
        int pos = sh[tid] - cnt;
        int* dst = (set == 0) ? g_split_idx : g_discard_idx;
        #pragma unroll
        for (int q = 0; q < 8; q++) {
            if (fl[q]) dst[b * MAXSEL + pos++] = n0 + q;
        }
        __syncthreads();
    }
    if (tid == 0) g_mc[b] = mc;
}

// -------------------- pair GEMM: z = relu(x[split]@ws + bs); z1 -> split row, z2 -> paired discard row --------------------
__global__ void __launch_bounds__(128) pair_gemm_kernel(
    const float* __restrict__ x, const float* __restrict__ ws,
    const float* __restrict__ bsv, float* __restrict__ out)
{
    int b = blockIdx.z;
    int mc = g_mc[b];
    int i0 = blockIdx.y * BM;
    if (i0 >= mc) return;
    int nb0 = blockIdx.x * BN;        // 0,128,256,384
    int half = nb0 >> 8;              // 0 -> z1 (store at split row), 1 -> z2 (store at discard row)

    __shared__ float As[BK][BM];
    __shared__ float Bs[BK][BN];
    __shared__ float bss[BN];
    __shared__ int srcI[BM];
    __shared__ int tgtI[BM];

    int tid = threadIdx.x;
    if (tid < BN) bss[tid] = bsv[nb0 + tid];
    if (tid < BM) {
        int i = i0 + tid;
        if (i < mc) {
            int m = g_split_idx[b * MAXSEL + i];
            srcI[tid] = m;
            tgtI[tid] = half ? g_discard_idx[b * MAXSEL + i] : m;
        } else { srcI[tid] = 0; tgtI[tid] = -1; }
    }
    __syncthreads();

    int rg = tid >> 4, cg = tid & 15;
    float acc[8][8];
    #pragma unroll
    for (int i = 0; i < 8; i++)
        #pragma unroll
        for (int j = 0; j < 8; j++) acc[i][j] = 0.f;

    for (int kt = 0; kt < CC; kt += BK) {
        #pragma unroll
        for (int r = 0; r < 2; r++) {
            int q = tid + r * 128;
            int row = q >> 2, c4 = q & 3;
            float4 v = *(const float4*)&x[(srcI[row] * BB + b) * CC + kt + c4 * 4];
            As[c4*4+0][row] = v.x; As[c4*4+1][row] = v.y;
            As[c4*4+2][row] = v.z; As[c4*4+3][row] = v.w;
        }
        #pragma unroll
        for (int r = 0; r < 4; r++) {
            int q = tid + r * 128;
            int krow = q >> 5, c4 = q & 31;
            *(float4*)&Bs[krow][c4*4] = *(const float4*)&ws[(kt + krow) * C2 + nb0 + c4 * 4];
        }
        __syncthreads();
        #pragma unroll
        for (int kk = 0; kk < BK; kk++) {
            float a[8], bb[8];
            *(float4*)&a[0]  = *(float4*)&As[kk][rg*8];
            *(float4*)&a[4]  = *(float4*)&As[kk][rg*8+4];
            *(float4*)&bb[0] = *(float4*)&Bs[kk][cg*8];
            *(float4*)&bb[4] = *(float4*)&Bs[kk][cg*8+4];
            #pragma unroll
            for (int i = 0; i < 8; i++)
                #pragma unroll
                for (int j = 0; j < 8; j++)
                    acc[i][j] = fmaf(a[i], bb[j], acc[i][j]);
        }
        __syncthreads();
    }

    int colb = (nb0 + cg * 8) & (CC - 1);
    #pragma unroll
    for (int i = 0; i < 8; i++) {
        int r = rg * 8 + i;
        int tg = tgtI[r];
        if (tg < 0) continue;
        float v[8];
        #pragma unroll
        for (int j = 0; j < 8; j++) v[j] = fmaxf(acc[i][j] + bss[cg*8+j], 0.f);
        float* o = &out[(tg * BB + b) * CC + colb];
        *(float4*)&o[0] = *(float4*)&v[0];
        *(float4*)&o[4] = *(float4*)&v[4];
    }
}

// -------------------- launch --------------------
extern "C" void kernel_launch(void* const* d_in, const int* in_sizes, int n_in,
                              void* d_out, int out_size) {
    const float* x   = (const float*)d_in[0];
    const void*  msk = d_in[1];
    const float* w1  = (const float*)d_in[2];
    const float* b1  = (const float*)d_in[3];
    const float* w2  = (const float*)d_in[4];
    const float* b2  = (const float*)d_in[5];
    const float* ws  = (const float*)d_in[6];
    const float* bs  = (const float*)d_in[7];
    float* out = (float*)d_out;

    detect_mask_kernel<<<1, 256>>>((const unsigned char*)msk);
    expand_mask_kernel<<<NTOK / 256, 256>>>(msk);

    // default: out = x (kept rows); selected rows overwritten by pair_gemm
    cudaMemcpyAsync(out, x, (size_t)NTOK * CC * sizeof(float),
                    cudaMemcpyDeviceToDevice, 0);

    gating_kernel<<<NTOK / BM, 128>>>(x, w1, b1, w2, b2);
    select_kernel<<<BB, 512>>>();
    pair_gemm_kernel<<<dim3(C2 / BN, MAXSEL / BM, BB), 128>>>(x, ws, bs, out);
}

// round 4
// speedup vs baseline: 1.1764x; 1.1764x over previous
#include <cuda_runtime.h>
#include <cuda_bf16.h>
#include <cstdint>

// Problem constants
#define NN 4096
#define BB 16
#define CC 256
#define HH 128
#define C2 512
#define NTOK (NN*BB)       // 65536
#define MAXSEL 2048        // min_cnt <= N/2

// GEMM tiling (128x128 tiles, 256 threads, 8x8 per thread, BK=16, double buffered)
#define GBM 128
#define GBN 128
#define GBK 16

// -------------------- device scratch --------------------
__device__ float g_sig[NTOK];                 // [b][n]
__device__ unsigned char g_valid[NTOK];       // [b][n]
__device__ unsigned char g_selflag[NTOK];     // [b][n] 1 = row overwritten by pair gemm
__device__ int g_mask_kind;                   // 0=u8, 1=i32, 2=f32
__device__ int g_split_idx[BB*MAXSEL];
__device__ int g_discard_idx[BB*MAXSEL];
__device__ int g_mc[BB];

// -------------------- mask dtype detection --------------------
__global__ void detect_mask_kernel(const unsigned char* __restrict__ m) {
    __shared__ int f3, foff;
    if (threadIdx.x == 0) { f3 = 0; foff = 0; }
    __syncthreads();
    int l3 = 0, loff = 0;
    for (int i = threadIdx.x; i < NTOK; i += 1024) {
        unsigned char v = m[i];
        if (v == 0x3f) l3 = 1;
        if (v && (i & 3)) loff = 1;
    }
    if (l3) f3 = 1;
    if (loff) foff = 1;
    __syncthreads();
    if (threadIdx.x == 0) g_mask_kind = f3 ? 2 : (foff ? 0 : 1);
}

__global__ void expand_mask_kernel(const void* __restrict__ m) {
    int i = blockIdx.x * 256 + threadIdx.x;
    if (i >= NTOK) return;
    int kind = g_mask_kind;
    int v;
    if (kind == 0)      v = ((const unsigned char*)m)[i];
    else if (kind == 1) v = ((const int*)m)[i];
    else                v = (((const float*)m)[i] != 0.0f);
    g_valid[i] = (v == 0) ? 1 : 0;   // valid = ~mask
    g_selflag[i] = 0;
}

// -------------------- gating: sig = sigmoid(relu(x@w1+b1)@w2 + b2) --------------------
// NOTE: accumulation order over k is identical to R1 (kt ascending, kk ascending)
// so g_sig is bitwise identical -> selection exactness preserved.
__global__ void __launch_bounds__(256) gating_kernel(
    const float* __restrict__ x, const float* __restrict__ w1,
    const float* __restrict__ b1v, const float* __restrict__ w2v,
    const float* __restrict__ b2v)
{
    __shared__ float As[2][GBK][GBM];
    __shared__ float Bs[2][GBK][GBN];
    __shared__ float w2s[HH];
    __shared__ float b1s[HH];
    __shared__ float red[GBM][17];

    int tid = threadIdx.x;
    int rg = tid >> 4, cg = tid & 15;
    int tM = blockIdx.x * GBM;

    if (tid < HH) { w2s[tid] = w2v[tid]; b1s[tid] = b1v[tid]; }

    int a_row = tid >> 2;          // 0..63
    int a_c4  = (tid & 3) * 4;     // 0,4,8,12
    int b_k   = tid >> 5;          // 0..7
    int b_c   = (tid & 31) * 4;    // 0..124

    float4 aR0, aR1, bR0, bR1;

#define GLOAD(kt) { \
    aR0 = *(const float4*)&x[(tM + a_row) * CC + (kt) + a_c4]; \
    aR1 = *(const float4*)&x[(tM + 64 + a_row) * CC + (kt) + a_c4]; \
    bR0 = *(const float4*)&w1[((kt) + b_k) * HH + b_c]; \
    bR1 = *(const float4*)&w1[((kt) + 8 + b_k) * HH + b_c]; }

#define SSTORE(db) { \
    As[db][a_c4+0][a_row] = aR0.x; As[db][a_c4+1][a_row] = aR0.y; \
    As[db][a_c4+2][a_row] = aR0.z; As[db][a_c4+3][a_row] = aR0.w; \
    As[db][a_c4+0][64+a_row] = aR1.x; As[db][a_c4+1][64+a_row] = aR1.y; \
    As[db][a_c4+2][64+a_row] = aR1.z; As[db][a_c4+3][64+a_row] = aR1.w; \
    *(float4*)&Bs[db][b_k][b_c] = bR0; \
    *(float4*)&Bs[db][8+b_k][b_c] = bR1; }

#define GCOMP(db) { \
    _Pragma("unroll") \
    for (int kk = 0; kk < GBK; kk++) { \
        float a_[8], bb_[8]; \
        *(float4*)&a_[0]  = *(const float4*)&As[db][kk][rg*8]; \
        *(float4*)&a_[4]  = *(const float4*)&As[db][kk][rg*8+4]; \
        *(float4*)&bb_[0] = *(const float4*)&Bs[db][kk][cg*8]; \
        *(float4*)&bb_[4] = *(const float4*)&Bs[db][kk][cg*8+4]; \
        _Pragma("unroll") \
        for (int i_ = 0; i_ < 8; i_++) \
            _Pragma("unroll") \
            for (int j_ = 0; j_ < 8; j_++) \
                acc[i_][j_] = fmaf(a_[i_], bb_[j_], acc[i_][j_]); \
    } }

    float acc[8][8];
    #pragma unroll
    for (int i = 0; i < 8; i++)
        #pragma unroll
        for (int j = 0; j < 8; j++) acc[i][j] = 0.f;

    GLOAD(0); SSTORE(0); __syncthreads();
    int db = 0;
    for (int kt = GBK; kt < CC; kt += GBK) {
        GLOAD(kt);
        GCOMP(db);
        SSTORE(db ^ 1);
        __syncthreads();
        db ^= 1;
    }
    GCOMP(db);

    // epilogue: relu(h + b1) dot w2
    #pragma unroll
    for (int i = 0; i < 8; i++) {
        float p = 0.f;
        #pragma unroll
        for (int j = 0; j < 8; j++) {
            float h = fmaxf(acc[i][j] + b1s[cg*8+j], 0.f);
            p = fmaf(h, w2s[cg*8+j], p);
        }
        red[rg*8+i][cg] = p;
    }
    __syncthreads();
    if (tid < GBM) {
        float lg = b2v[0];
        #pragma unroll
        for (int g = 0; g < 16; g++) lg += red[tid][g];
        float s;
        if (lg >= 0.f) { s = 1.f / (1.f + expf(-lg)); }
        else           { float e = expf(lg); s = e / (1.f + e); }
        int t = tM + tid;              // global row = n*B + b
        g_sig[(t & (BB-1)) * NN + (t >> 4)] = s;
    }
#undef GLOAD
#undef SSTORE
#undef GCOMP
}

// -------------------- selection: 3-pass radix select (12/10/10 bits) per (batch,set) --------------------
__global__ void __launch_bounds__(512) select_kernel() {
    const int T = 512;
    int set = blockIdx.x;              // 0 = split, 1 = discard
    int b = blockIdx.y;
    int tid = threadIdx.x;

    __shared__ int hist[4096];
    __shared__ int sh[T];
    __shared__ int s_scal[8];          // 0:s_cnt 1:d_cnt 2:chunk 3:digit 4:k

    const float* sig = g_sig + b * NN;
    const unsigned char* vd = g_valid + b * NN;

    if (tid < 8) s_scal[tid] = 0;
    __syncthreads();
    int cs = 0, cd = 0;
    for (int n = tid; n < NN; n += T) {
        if (vd[n]) { if (sig[n] >= 0.5f) cs++; else cd++; }
    }
    #pragma unroll
    for (int o = 16; o; o >>= 1) {
        cs += __shfl_down_sync(~0u, cs, o);
        cd += __shfl_down_sync(~0u, cd, o);
    }
    if ((tid & 31) == 0) { atomicAdd(&s_scal[0], cs); atomicAdd(&s_scal[1], cd); }
    __syncthreads();
    int mc = min(s_scal[0], s_scal[1]);
    if (set == 0 && tid == 0) g_mc[b] = mc;
    if (mc == 0) return;

    int k = mc;
    unsigned thrV = 0;
    unsigned hm = 0;
    const int widths[3] = {12, 10, 10};
    const int shifts[3] = {20, 10, 0};

    for (int p = 0; p < 3; p++) {
        int shift = shifts[p];
        int nb2 = 1 << widths[p];
        int CHn = nb2 >> 9;            // bins per thread: 8 or 2
        for (int i = tid; i < nb2; i += T) hist[i] = 0;
        __syncthreads();
        for (int n = tid; n < NN; n += T) {
            if (!vd[n]) continue;
            float s = sig[n];
            bool in = set ? (s < 0.5f) : (s >= 0.5f);
            if (!in) continue;
            unsigned bits = __float_as_uint(s);
            if ((bits & hm) != thrV) continue;
            atomicAdd(&hist[(bits >> shift) & (nb2 - 1)], 1);
        }
        __syncthreads();
        // per-thread chunk sums
        int base = tid * CHn, csum = 0;
        for (int i = 0; i < CHn; i++) csum += hist[base + i];
        sh[tid] = csum;
        __syncthreads();
        // suffix scan over chunks
        for (int off = 1; off < T; off <<= 1) {
            int v = sh[tid];
            int o2 = (tid + off < T) ? sh[tid + off] : 0;
            __syncthreads();
            sh[tid] = v + o2;
            __syncthreads();
        }
        // find crossing chunk: largest c with S(c) >= k
        {
            int Sc = sh[tid];
            int Scn = (tid + 1 < T) ? sh[tid + 1] : 0;
            if (Sc >= k && Scn < k) s_scal[2] = tid;
        }
        __syncthreads();
        if (tid == 0) {
            int cc = s_scal[2];
            int above = (cc + 1 < T) ? sh[cc + 1] : 0;
            int dg = cc * CHn;
            for (int d = cc * CHn + CHn - 1; d >= cc * CHn; d--) {
                int c = hist[d];
                if (above + c >= k) { dg = d; break; }
                above += c;
            }
            s_scal[3] = dg;
            s_scal[4] = k - above;
        }
        __syncthreads();
        thrV |= ((unsigned)s_scal[3]) << shift;
        k = s_scal[4];
        hm |= ((unsigned)(nb2 - 1)) << shift;
        __syncthreads();
    }
    int k_rem = k;   // take first k_rem (by index) among sig-bits == thrV

    // compaction: index-ordered, packed (gt | eq<<16) prefix scan
    int n0 = tid * 8;
    unsigned char gtf[8], eqf[8];
    int lgt = 0, leq = 0;
    #pragma unroll
    for (int q = 0; q < 8; q++) {
        int n = n0 + q;
        float s = sig[n];
        bool in = vd[n] && (set ? (s < 0.5f) : (s >= 0.5f));
        unsigned bits = __float_as_uint(s);
        gtf[q] = (in && bits > thrV) ? 1 : 0;
        eqf[q] = (in && bits == thrV) ? 1 : 0;
        lgt += gtf[q]; leq += eqf[q];
    }
    int own = lgt | (leq << 16);
    sh[tid] = own;
    __syncthreads();
    for (int off = 1; off < T; off <<= 1) {
        int v = sh[tid];
        int o2 = (tid >= off) ? sh[tid - off] : 0;
        __syncthreads();
        sh[tid] = v + o2;
        __syncthreads();
    }
    int pref = sh[tid] - own;          // exclusive
    int pgt = pref & 0xFFFF, peq = pref >> 16;
    int* dst = set ? g_discard_idx : g_split_idx;
    unsigned char* flag = g_selflag + b * NN;
    int cgi = 0, cei = 0;
    #pragma unroll
    for (int q = 0; q < 8; q++) {
        int n = n0 + q;
        if (gtf[q]) {
            int pos = (pgt + cgi) + min(peq + cei, k_rem);
            dst[b * MAXSEL + pos] = n;
            flag[n] = 1;
            cgi++;
        } else if (eqf[q]) {
            int er = peq + cei;
            if (er < k_rem) {
                int pos = (pgt + cgi) + er;
                dst[b * MAXSEL + pos] = n;
                flag[n] = 1;
            }
            cei++;
        }
    }
}

// -------------------- flag-gated copy: out = x for rows not overwritten by pair gemm --------------------
__global__ void __launch_bounds__(256) copyx_kernel(
    const float4* __restrict__ x4, float4* __restrict__ out4)
{
    int idx = blockIdx.x * 256 + threadIdx.x;    // NTOK*64 float4 total
    int t = idx >> 6;
    int b = t & (BB - 1), n = t >> 4;
    if (!g_selflag[b * NN + n]) out4[idx] = x4[idx];
}

// -------------------- pair GEMM: z = relu(x[split]@ws + bs); z1 -> split row, z2 -> paired discard row --------------------
__global__ void __launch_bounds__(256) pair_gemm_kernel(
    const float* __restrict__ x, const float* __restrict__ ws,
    const float* __restrict__ bsv, float* __restrict__ out)
{
    int b = blockIdx.z;
    int mc = g_mc[b];
    int i0 = blockIdx.y * GBM;
    if (i0 >= mc) return;
    int nb0 = blockIdx.x * GBN;        // 0,128,256,384
    int half = nb0 >> 8;               // 0 -> z1 (split row), 1 -> z2 (paired discard row)

    __shared__ float As[2][GBK][GBM];
    __shared__ float Bs[2][GBK][GBN];
    __shared__ float bss[GBN];
    __shared__ int srcI[GBM];
    __shared__ int tgtI[GBM];

    int tid = threadIdx.x;
    if (tid < GBN) bss[tid] = bsv[nb0 + tid];
    if (tid < GBM) {
        int i = i0 + tid;
        if (i < mc) {
            int m = g_split_idx[b * MAXSEL + i];
            srcI[tid] = m;
            tgtI[tid] = half ? g_discard_idx[b * MAXSEL + i] : m;
        } else { srcI[tid] = 0; tgtI[tid] = -1; }
    }
    __syncthreads();

    int rg = tid >> 4, cg = tid & 15;
    int a_row = tid >> 2;
    int a_c4  = (tid & 3) * 4;
    int b_k   = tid >> 5;
    int b_c   = (tid & 31) * 4;

    float4 aR0, aR1, bR0, bR1;

#define PLOAD(kt) { \
    aR0 = *(const float4*)&x[(srcI[a_row] * BB + b) * CC + (kt) + a_c4]; \
    aR1 = *(const float4*)&x[(srcI[64 + a_row] * BB + b) * CC + (kt) + a_c4]; \
    bR0 = *(const float4*)&ws[((kt) + b_k) * C2 + nb0 + b_c]; \
    bR1 = *(const float4*)&ws[((kt) + 8 + b_k) * C2 + nb0 + b_c]; }

#define PSTORE(db) { \
    As[db][a_c4+0][a_row] = aR0.x; As[db][a_c4+1][a_row] = aR0.y; \
    As[db][a_c4+2][a_row] = aR0.z; As[db][a_c4+3][a_row] = aR0.w; \
    As[db][a_c4+0][64+a_row] = aR1.x; As[db][a_c4+1][64+a_row] = aR1.y; \
    As[db][a_c4+2][64+a_row] = aR1.z; As[db][a_c4+3][64+a_row] = aR1.w; \
    *(float4*)&Bs[db][b_k][b_c] = bR0; \
    *(float4*)&Bs[db][8+b_k][b_c] = bR1; }

#define PCOMP(db) { \
    _Pragma("unroll") \
    for (int kk = 0; kk < GBK; kk++) { \
        float a_[8], bb_[8]; \
        *(float4*)&a_[0]  = *(const float4*)&As[db][kk][rg*8]; \
        *(float4*)&a_[4]  = *(const float4*)&As[db][kk][rg*8+4]; \
        *(float4*)&bb_[0] = *(const float4*)&Bs[db][kk][cg*8]; \
        *(float4*)&bb_[4] = *(const float4*)&Bs[db][kk][cg*8+4]; \
        _Pragma("unroll") \
        for (int i_ = 0; i_ < 8; i_++) \
            _Pragma("unroll") \
            for (int j_ = 0; j_ < 8; j_++) \
                acc[i_][j_] = fmaf(a_[i_], bb_[j_], acc[i_][j_]); \
    } }

    float acc[8][8];
    #pragma unroll
    for (int i = 0; i < 8; i++)
        #pragma unroll
        for (int j = 0; j < 8; j++) acc[i][j] = 0.f;

    PLOAD(0); PSTORE(0); __syncthreads();
    int db = 0;
    for (int kt = GBK; kt < CC; kt += GBK) {
        PLOAD(kt);
        PCOMP(db);
        PSTORE(db ^ 1);
        __syncthreads();
        db ^= 1;
    }
    PCOMP(db);

    int colb = (nb0 + cg * 8) & (CC - 1);
    #pragma unroll
    for (int i = 0; i < 8; i++) {
        int r = rg * 8 + i;
        int tg = tgtI[r];
        if (tg < 0) continue;
        float v[8];
        #pragma unroll
        for (int j = 0; j < 8; j++) v[j] = fmaxf(acc[i][j] + bss[cg*8+j], 0.f);
        float* o = &out[(tg * BB + b) * CC + colb];
        *(float4*)&o[0] = *(float4*)&v[0];
        *(float4*)&o[4] = *(float4*)&v[4];
    }
#undef PLOAD
#undef PSTORE
#undef PCOMP
}

// -------------------- launch --------------------
extern "C" void kernel_launch(void* const* d_in, const int* in_sizes, int n_in,
                              void* d_out, int out_size) {
    const float* x   = (const float*)d_in[0];
    const void*  msk = d_in[1];
    const float* w1  = (const float*)d_in[2];
    const float* b1  = (const float*)d_in[3];
    const float* w2  = (const float*)d_in[4];
    const float* b2  = (const float*)d_in[5];
    const float* ws  = (const float*)d_in[6];
    const float* bs  = (const float*)d_in[7];
    float* out = (float*)d_out;

    detect_mask_kernel<<<1, 1024>>>((const unsigned char*)msk);
    expand_mask_kernel<<<NTOK / 256, 256>>>(msk);

    gating_kernel<<<NTOK / GBM, 256>>>(x, w1, b1, w2, b2);
    select_kernel<<<dim3(2, BB), 512>>>();
    copyx_kernel<<<(NTOK * (CC/4)) / 256, 256>>>((const float4*)x, (float4*)out);
    pair_gemm_kernel<<<dim3(C2 / GBN, MAXSEL / GBM, BB), 256>>>(x, ws, bs, out);
}

// round 5
// speedup vs baseline: 1.5428x; 1.3114x over previous
#include <cuda_runtime.h>
#include <cuda_bf16.h>
#include <cstdint>

// Problem constants
#define NN 4096
#define BB 16
#define CC 256
#define HH 128
#define C2 512
#define NTOK (NN*BB)       // 65536
#define MAXSEL 2048        // min_cnt <= N/2

// fp32 gating GEMM tiling (unchanged: bit-identical g_sig)
#define GBM 128
#define GBN 128
#define GBK 16

// -------------------- device scratch --------------------
__device__ float g_sig[NTOK];                 // [b][n]
__device__ unsigned char g_valid[NTOK];       // [b][n]
__device__ unsigned char g_selflag[NTOK];     // [b][n]
__device__ int g_mask_kind;
__device__ int g_split_idx[BB*MAXSEL];
__device__ int g_discard_idx[BB*MAXSEL];
__device__ int g_mc[BB];
__device__ __nv_bfloat16 g_ws_hi[CC*C2];      // pre-split ws
__device__ __nv_bfloat16 g_ws_lo[CC*C2];

// -------------------- mask dtype detection --------------------
__global__ void detect_mask_kernel(const unsigned char* __restrict__ m) {
    __shared__ int f3, foff;
    if (threadIdx.x == 0) { f3 = 0; foff = 0; }
    __syncthreads();
    int l3 = 0, loff = 0;
    for (int i = threadIdx.x; i < NTOK; i += 1024) {
        unsigned char v = m[i];
        if (v == 0x3f) l3 = 1;
        if (v && (i & 3)) loff = 1;
    }
    if (l3) f3 = 1;
    if (loff) foff = 1;
    __syncthreads();
    if (threadIdx.x == 0) g_mask_kind = f3 ? 2 : (foff ? 0 : 1);
}

__global__ void expand_mask_kernel(const void* __restrict__ m) {
    int i = blockIdx.x * 256 + threadIdx.x;
    if (i >= NTOK) return;
    int kind = g_mask_kind;
    int v;
    if (kind == 0)      v = ((const unsigned char*)m)[i];
    else if (kind == 1) v = ((const int*)m)[i];
    else                v = (((const float*)m)[i] != 0.0f);
    g_valid[i] = (v == 0) ? 1 : 0;
    g_selflag[i] = 0;
}

// -------------------- ws pre-split: fp32 -> bf16 hi + bf16 lo --------------------
__global__ void prep_ws_kernel(const float* __restrict__ ws) {
    int i = blockIdx.x * 256 + threadIdx.x;
    if (i >= CC * C2) return;
    float w = ws[i];
    __nv_bfloat16 h = __float2bfloat16(w);
    g_ws_hi[i] = h;
    g_ws_lo[i] = __float2bfloat16(w - __bfloat162float(h));
}

// -------------------- gating (fp32, bit-identical to R1) --------------------
__global__ void __launch_bounds__(256) gating_kernel(
    const float* __restrict__ x, const float* __restrict__ w1,
    const float* __restrict__ b1v, const float* __restrict__ w2v,
    const float* __restrict__ b2v)
{
    __shared__ float As[2][GBK][GBM];
    __shared__ float Bs[2][GBK][GBN];
    __shared__ float w2s[HH];
    __shared__ float b1s[HH];
    __shared__ float red[GBM][17];

    int tid = threadIdx.x;
    int rg = tid >> 4, cg = tid & 15;
    int tM = blockIdx.x * GBM;

    if (tid < HH) { w2s[tid] = w2v[tid]; b1s[tid] = b1v[tid]; }

    int a_row = tid >> 2;
    int a_c4  = (tid & 3) * 4;
    int b_k   = tid >> 5;
    int b_c   = (tid & 31) * 4;

    float4 aR0, aR1, bR0, bR1;

#define GLOAD(kt) { \
    aR0 = *(const float4*)&x[(tM + a_row) * CC + (kt) + a_c4]; \
    aR1 = *(const float4*)&x[(tM + 64 + a_row) * CC + (kt) + a_c4]; \
    bR0 = *(const float4*)&w1[((kt) + b_k) * HH + b_c]; \
    bR1 = *(const float4*)&w1[((kt) + 8 + b_k) * HH + b_c]; }

#define SSTORE(db) { \
    As[db][a_c4+0][a_row] = aR0.x; As[db][a_c4+1][a_row] = aR0.y; \
    As[db][a_c4+2][a_row] = aR0.z; As[db][a_c4+3][a_row] = aR0.w; \
    As[db][a_c4+0][64+a_row] = aR1.x; As[db][a_c4+1][64+a_row] = aR1.y; \
    As[db][a_c4+2][64+a_row] = aR1.z; As[db][a_c4+3][64+a_row] = aR1.w; \
    *(float4*)&Bs[db][b_k][b_c] = bR0; \
    *(float4*)&Bs[db][8+b_k][b_c] = bR1; }

#define GCOMP(db) { \
    _Pragma("unroll") \
    for (int kk = 0; kk < GBK; kk++) { \
        float a_[8], bb_[8]; \
        *(float4*)&a_[0]  = *(const float4*)&As[db][kk][rg*8]; \
        *(float4*)&a_[4]  = *(const float4*)&As[db][kk][rg*8+4]; \
        *(float4*)&bb_[0] = *(const float4*)&Bs[db][kk][cg*8]; \
        *(float4*)&bb_[4] = *(const float4*)&Bs[db][kk][cg*8+4]; \
        _Pragma("unroll") \
        for (int i_ = 0; i_ < 8; i_++) \
            _Pragma("unroll") \
            for (int j_ = 0; j_ < 8; j_++) \
                acc[i_][j_] = fmaf(a_[i_], bb_[j_], acc[i_][j_]); \
    } }

    float acc[8][8];
    #pragma unroll
    for (int i = 0; i < 8; i++)
        #pragma unroll
        for (int j = 0; j < 8; j++) acc[i][j] = 0.f;

    GLOAD(0); SSTORE(0); __syncthreads();
    int db = 0;
    for (int kt = GBK; kt < CC; kt += GBK) {
        GLOAD(kt);
        GCOMP(db);
        SSTORE(db ^ 1);
        __syncthreads();
        db ^= 1;
    }
    GCOMP(db);

    #pragma unroll
    for (int i = 0; i < 8; i++) {
        float p = 0.f;
        #pragma unroll
        for (int j = 0; j < 8; j++) {
            float h = fmaxf(acc[i][j] + b1s[cg*8+j], 0.f);
            p = fmaf(h, w2s[cg*8+j], p);
        }
        red[rg*8+i][cg] = p;
    }
    __syncthreads();
    if (tid < GBM) {
        float lg = b2v[0];
        #pragma unroll
        for (int g = 0; g < 16; g++) lg += red[tid][g];
        float s;
        if (lg >= 0.f) { s = 1.f / (1.f + expf(-lg)); }
        else           { float e = expf(lg); s = e / (1.f + e); }
        int t = tM + tid;
        g_sig[(t & (BB-1)) * NN + (t >> 4)] = s;
    }
#undef GLOAD
#undef SSTORE
#undef GCOMP
}

// -------------------- selection: 3-pass radix select (12/10/10 bits) --------------------
__global__ void __launch_bounds__(512) select_kernel() {
    const int T = 512;
    int set = blockIdx.x;
    int b = blockIdx.y;
    int tid = threadIdx.x;

    __shared__ int hist[4096];
    __shared__ int sh[T];
    __shared__ int s_scal[8];

    const float* sig = g_sig + b * NN;
    const unsigned char* vd = g_valid + b * NN;

    if (tid < 8) s_scal[tid] = 0;
    __syncthreads();
    int cs = 0, cd = 0;
    for (int n = tid; n < NN; n += T) {
        if (vd[n]) { if (sig[n] >= 0.5f) cs++; else cd++; }
    }
    #pragma unroll
    for (int o = 16; o; o >>= 1) {
        cs += __shfl_down_sync(~0u, cs, o);
        cd += __shfl_down_sync(~0u, cd, o);
    }
    if ((tid & 31) == 0) { atomicAdd(&s_scal[0], cs); atomicAdd(&s_scal[1], cd); }
    __syncthreads();
    int mc = min(s_scal[0], s_scal[1]);
    if (set == 0 && tid == 0) g_mc[b] = mc;
    if (mc == 0) return;

    int k = mc;
    unsigned thrV = 0;
    unsigned hm = 0;
    const int widths[3] = {12, 10, 10};
    const int shifts[3] = {20, 10, 0};

    for (int p = 0; p < 3; p++) {
        int shift = shifts[p];
        int nb2 = 1 << widths[p];
        int CHn = nb2 >> 9;
        for (int i = tid; i < nb2; i += T) hist[i] = 0;
        __syncthreads();
        for (int n = tid; n < NN; n += T) {
            if (!vd[n]) continue;
            float s = sig[n];
            bool in = set ? (s < 0.5f) : (s >= 0.5f);
            if (!in) continue;
            unsigned bits = __float_as_uint(s);
            if ((bits & hm) != thrV) continue;
            atomicAdd(&hist[(bits >> shift) & (nb2 - 1)], 1);
        }
        __syncthreads();
        int base = tid * CHn, csum = 0;
        for (int i = 0; i < CHn; i++) csum += hist[base + i];
        sh[tid] = csum;
        __syncthreads();
        for (int off = 1; off < T; off <<= 1) {
            int v = sh[tid];
            int o2 = (tid + off < T) ? sh[tid + off] : 0;
            __syncthreads();
            sh[tid] = v + o2;
            __syncthreads();
        }
        {
            int Sc = sh[tid];
            int Scn = (tid + 1 < T) ? sh[tid + 1] : 0;
            if (Sc >= k && Scn < k) s_scal[2] = tid;
        }
        __syncthreads();
        if (tid == 0) {
            int cc = s_scal[2];
            int above = (cc + 1 < T) ? sh[cc + 1] : 0;
            int dg = cc * CHn;
            for (int d = cc * CHn + CHn - 1; d >= cc * CHn; d--) {
                int c = hist[d];
                if (above + c >= k) { dg = d; break; }
                above += c;
            }
            s_scal[3] = dg;
            s_scal[4] = k - above;
        }
        __syncthreads();
        thrV |= ((unsigned)s_scal[3]) << shift;
        k = s_scal[4];
        hm |= ((unsigned)(nb2 - 1)) << shift;
        __syncthreads();
    }
    int k_rem = k;

    int n0 = tid * 8;
    unsigned char gtf[8], eqf[8];
    int lgt = 0, leq = 0;
    #pragma unroll
    for (int q = 0; q < 8; q++) {
        int n = n0 + q;
        float s = sig[n];
        bool in = vd[n] && (set ? (s < 0.5f) : (s >= 0.5f));
        unsigned bits = __float_as_uint(s);
        gtf[q] = (in && bits > thrV) ? 1 : 0;
        eqf[q] = (in && bits == thrV) ? 1 : 0;
        lgt += gtf[q]; leq += eqf[q];
    }
    int own = lgt | (leq << 16);
    sh[tid] = own;
    __syncthreads();
    for (int off = 1; off < T; off <<= 1) {
        int v = sh[tid];
        int o2 = (tid >= off) ? sh[tid - off] : 0;
        __syncthreads();
        sh[tid] = v + o2;
        __syncthreads();
    }
    int pref = sh[tid] - own;
    int pgt = pref & 0xFFFF, peq = pref >> 16;
    int* dst = set ? g_discard_idx : g_split_idx;
    unsigned char* flag = g_selflag + b * NN;
    int cgi = 0, cei = 0;
    #pragma unroll
    for (int q = 0; q < 8; q++) {
        int n = n0 + q;
        if (gtf[q]) {
            int pos = (pgt + cgi) + min(peq + cei, k_rem);
            dst[b * MAXSEL + pos] = n;
            flag[n] = 1;
            cgi++;
        } else if (eqf[q]) {
            int er = peq + cei;
            if (er < k_rem) {
                int pos = (pgt + cgi) + er;
                dst[b * MAXSEL + pos] = n;
                flag[n] = 1;
            }
            cei++;
        }
    }
}

// -------------------- flag-gated copy --------------------
__global__ void __launch_bounds__(256) copyx_kernel(
    const float4* __restrict__ x4, float4* __restrict__ out4)
{
    int idx = blockIdx.x * 256 + threadIdx.x;
    int t = idx >> 6;
    int b = t & (BB - 1), n = t >> 4;
    if (!g_selflag[b * NN + n]) out4[idx] = x4[idx];
}

// -------------------- mma helpers --------------------
__device__ __forceinline__ uint32_t smem_u32(const void* p) {
    return (uint32_t)__cvta_generic_to_shared(p);
}
__device__ __forceinline__ void ldsm_x4(uint32_t& r0, uint32_t& r1, uint32_t& r2, uint32_t& r3, uint32_t addr) {
    asm volatile("ldmatrix.sync.aligned.m8n8.x4.shared.b16 {%0,%1,%2,%3}, [%4];"
                 : "=r"(r0), "=r"(r1), "=r"(r2), "=r"(r3) : "r"(addr));
}
__device__ __forceinline__ void ldsm_x4t(uint32_t& r0, uint32_t& r1, uint32_t& r2, uint32_t& r3, uint32_t addr) {
    asm volatile("ldmatrix.sync.aligned.m8n8.x4.trans.shared.b16 {%0,%1,%2,%3}, [%4];"
                 : "=r"(r0), "=r"(r1), "=r"(r2), "=r"(r3) : "r"(addr));
}
__device__ __forceinline__ void mma_bf16(float* d, const uint32_t* a, const uint32_t* bfr) {
    asm volatile("mma.sync.aligned.m16n8k16.row.col.f32.bf16.bf16.f32 "
                 "{%0,%1,%2,%3},{%4,%5,%6,%7},{%8,%9},{%0,%1,%2,%3};"
                 : "+f"(d[0]), "+f"(d[1]), "+f"(d[2]), "+f"(d[3])
                 : "r"(a[0]), "r"(a[1]), "r"(a[2]), "r"(a[3]), "r"(bfr[0]), "r"(bfr[1]));
}

// -------------------- pair GEMM on tensor cores (bf16x2 split, 3 products) --------------------
// Block: 64 split-rows x 128 out-cols, 256 threads (8 warps = 2Mx4N of 32x32 warp tiles)
__global__ void __launch_bounds__(256) pair_mma_kernel(
    const float* __restrict__ x, const float* __restrict__ bsv, float* __restrict__ out)
{
    int b = blockIdx.z;
    int mc = g_mc[b];
    int i0 = blockIdx.y * 64;
    if (i0 >= mc) return;
    int nb0 = blockIdx.x * 128;
    int half = nb0 >> 8;

    __shared__ __nv_bfloat16 sAhi[64][40], sAlo[64][40];     // LDA=40 (conflict-free ldmatrix)
    __shared__ __nv_bfloat16 sBhi[32][136], sBlo[32][136];   // LDB=136
    __shared__ float bss[128];
    __shared__ int srcI[64], tgtI[64];

    int tid = threadIdx.x;
    int lane = tid & 31;
    int wid = tid >> 5;

    if (tid < 128) bss[tid] = bsv[nb0 + tid];
    if (tid < 64) {
        int i = i0 + tid;
        if (i < mc) {
            int m = g_split_idx[b * MAXSEL + i];
            srcI[tid] = m;
            tgtI[tid] = half ? g_discard_idx[b * MAXSEL + i] : m;
        } else { srcI[tid] = 0; tgtI[tid] = -1; }
    }
    __syncthreads();

    int m_off = (wid >> 2) * 32;
    int n_off = (wid & 3) * 32;

    float acc[2][4][4];
    #pragma unroll
    for (int m = 0; m < 2; m++)
        #pragma unroll
        for (int j = 0; j < 4; j++)
            #pragma unroll
            for (int q = 0; q < 4; q++) acc[m][j][q] = 0.f;

    // A load role: thread -> (row 0..63, seg 0..3 of 8 floats)
    int ar = tid >> 2, aseg = (tid & 3) * 8;
    const float* xrow = &x[(srcI[ar] * BB + b) * CC + aseg];
    // B load role: thread -> (row 0..31, seg 0..7 of 16 bf16)
    int br = tid >> 3, bcol = (tid & 7) * 16;

    for (int kt = 0; kt < CC; kt += 32) {
        // ---- A: gather fp32, split to bf16 hi/lo ----
        float4 f0 = *(const float4*)&xrow[kt];
        float4 f1 = *(const float4*)&xrow[kt + 4];
        float fv[8] = {f0.x, f0.y, f0.z, f0.w, f1.x, f1.y, f1.z, f1.w};
        __nv_bfloat162 hp[4], lp[4];
        #pragma unroll
        for (int q = 0; q < 4; q++) {
            __nv_bfloat16 h0 = __float2bfloat16(fv[2*q]);
            __nv_bfloat16 h1 = __float2bfloat16(fv[2*q+1]);
            __nv_bfloat16 l0 = __float2bfloat16(fv[2*q]   - __bfloat162float(h0));
            __nv_bfloat16 l1 = __float2bfloat16(fv[2*q+1] - __bfloat162float(h1));
            hp[q] = __nv_bfloat162(h0, h1);
            lp[q] = __nv_bfloat162(l0, l1);
        }
        *(uint4*)&sAhi[ar][aseg] = *(uint4*)hp;
        *(uint4*)&sAlo[ar][aseg] = *(uint4*)lp;
        // ---- B: pre-split bf16 ----
        const __nv_bfloat16* bh = &g_ws_hi[(kt + br) * C2 + nb0 + bcol];
        const __nv_bfloat16* bl = &g_ws_lo[(kt + br) * C2 + nb0 + bcol];
        *(uint4*)&sBhi[br][bcol]     = *(const uint4*)&bh[0];
        *(uint4*)&sBhi[br][bcol + 8] = *(const uint4*)&bh[8];
        *(uint4*)&sBlo[br][bcol]     = *(const uint4*)&bl[0];
        *(uint4*)&sBlo[br][bcol + 8] = *(const uint4*)&bl[8];
        __syncthreads();

        #pragma unroll
        for (int ks = 0; ks < 2; ks++) {
            uint32_t ahi[2][4], alo[2][4], bhi[4][2], blo[4][2];
            #pragma unroll
            for (int m = 0; m < 2; m++) {
                int arow = m_off + m * 16 + (lane & 15);
                int acol = ks * 16 + (lane >> 4) * 8;
                ldsm_x4(ahi[m][0], ahi[m][1], ahi[m][2], ahi[m][3], smem_u32(&sAhi[arow][acol]));
                ldsm_x4(alo[m][0], alo[m][1], alo[m][2], alo[m][3], smem_u32(&sAlo[arow][acol]));
            }
            #pragma unroll
            for (int g = 0; g < 2; g++) {
                int brow = ks * 16 + (lane & 15);
                int bcl = n_off + g * 16 + (lane >> 4) * 8;
                uint32_t r0, r1, r2, r3;
                ldsm_x4t(r0, r1, r2, r3, smem_u32(&sBhi[brow][bcl]));
                bhi[2*g][0] = r0; bhi[2*g][1] = r1; bhi[2*g+1][0] = r2; bhi[2*g+1][1] = r3;
                ldsm_x4t(r0, r1, r2, r3, smem_u32(&sBlo[brow][bcl]));
                blo[2*g][0] = r0; blo[2*g][1] = r1; blo[2*g+1][0] = r2; blo[2*g+1][1] = r3;
            }
            #pragma unroll
            for (int m = 0; m < 2; m++)
                #pragma unroll
                for (int j = 0; j < 4; j++) {
                    mma_bf16(acc[m][j], ahi[m], bhi[j]);
                    mma_bf16(acc[m][j], ahi[m], blo[j]);
                    mma_bf16(acc[m][j], alo[m], bhi[j]);
                }
        }
        __syncthreads();
    }

    // ---- epilogue: bias + relu, scatter to target rows ----
    #pragma unroll
    for (int m = 0; m < 2; m++) {
        #pragma unroll
        for (int hr = 0; hr < 2; hr++) {
            int r = m_off + m * 16 + (lane >> 2) + hr * 8;
            int tg = tgtI[r];
            if (tg < 0) continue;
            float* orow = &out[(tg * BB + b) * CC];
            #pragma unroll
            for (int j = 0; j < 4; j++) {
                int cl = n_off + j * 8 + (lane & 3) * 2;       // local col in [0,128)
                int cg = (nb0 + cl) & (CC - 1);                 // out col
                float v0 = fmaxf(acc[m][j][hr*2]     + bss[cl],     0.f);
                float v1 = fmaxf(acc[m][j][hr*2 + 1] + bss[cl + 1], 0.f);
                float2 v = make_float2(v0, v1);
                *(float2*)&orow[cg] = v;
            }
        }
    }
}

// -------------------- launch --------------------
extern "C" void kernel_launch(void* const* d_in, const int* in_sizes, int n_in,
                              void* d_out, int out_size) {
    const float* x   = (const float*)d_in[0];
    const void*  msk = d_in[1];
    const float* w1  = (const float*)d_in[2];
    const float* b1  = (const float*)d_in[3];
    const float* w2  = (const float*)d_in[4];
    const float* b2  = (const float*)d_in[5];
    const float* ws  = (const float*)d_in[6];
    const float* bs  = (const float*)d_in[7];
    float* out = (float*)d_out;

    detect_mask_kernel<<<1, 1024>>>((const unsigned char*)msk);
    expand_mask_kernel<<<NTOK / 256, 256>>>(msk);
    prep_ws_kernel<<<(CC * C2) / 256, 256>>>(ws);

    gating_kernel<<<NTOK / GBM, 256>>>(x, w1, b1, w2, b2);
    select_kernel<<<dim3(2, BB), 512>>>();
    copyx_kernel<<<(NTOK * (CC/4)) / 256, 256>>>((const float4*)x, (float4*)out);
    pair_mma_kernel<<<dim3(4, MAXSEL / 64, BB), 256>>>(x, bs, out);
}